// round 11
// baseline (speedup 1.0000x reference)
#include <cuda_runtime.h>
#include <cuda_fp16.h>
#include <cstdint>

// B=1024, T=200, IN=H=128. rows = 204800.
__device__ __half g_xall16[(size_t)204800 * 384];   // [flat row][xu|xr|xg] fp16, biases folded
__device__ float g_logits[204800];
__device__ float g_att[204800];

__device__ __forceinline__ uint32_t smem_u32(const void* p) {
    return (uint32_t)__cvta_generic_to_shared(p);
}
__device__ __forceinline__ void ldmatrix_x4(uint32_t a[4], uint32_t addr) {
    asm volatile("ldmatrix.sync.aligned.m8n8.x4.shared.b16 {%0,%1,%2,%3}, [%4];"
                 : "=r"(a[0]), "=r"(a[1]), "=r"(a[2]), "=r"(a[3]) : "r"(addr));
}
__device__ __forceinline__ void mma16816(float c[4], const uint32_t a[4], uint32_t b0, uint32_t b1) {
    asm volatile("mma.sync.aligned.m16n8k16.row.col.f32.f16.f16.f32 "
                 "{%0,%1,%2,%3},{%4,%5,%6,%7},{%8,%9},{%0,%1,%2,%3};"
                 : "+f"(c[0]), "+f"(c[1]), "+f"(c[2]), "+f"(c[3])
                 : "r"(a[0]), "r"(a[1]), "r"(a[2]), "r"(a[3]), "r"(b0), "r"(b1));
}
__device__ __forceinline__ uint32_t f2h2(float x, float y) {
    __half2 h = __floats2half2_rn(x, y);
    return *reinterpret_cast<uint32_t*>(&h);
}
__device__ __forceinline__ float tanhapx(float x) {
    float y; asm("tanh.approx.f32 %0, %1;" : "=f"(y) : "f"(x)); return y;
}

// ================= K1: logits + x projections, register-resident weights =================
#define K1_HS_OFF  17408
#define K1_SWB_OFF 34816
#define K1_LGP_OFF 50176
#define K1_SMEM    51200
#define K1_TILES   3200

__global__ __launch_bounds__(512) void k1_ff(
    const float* __restrict__ targets, const float* __restrict__ hist,
    const float* __restrict__ Ww,  const float* __restrict__ Wb,
    const float* __restrict__ xuw, const float* __restrict__ xub,
    const float* __restrict__ xrw, const float* __restrict__ xrb,
    const float* __restrict__ xgw, const float* __restrict__ xgb)
{
    extern __shared__ char sm[];
    __half* tg16 = (__half*)sm;
    __half* hs16 = (__half*)(sm + K1_HS_OFF);
    uint32_t* swb = (uint32_t*)(sm + K1_SWB_OFF);
    float* lgp = (float*)(sm + K1_LGP_OFF);

    const int t = threadIdx.x, w = t >> 5, lane = t & 31;
    const int q = lane & 3, l4 = lane >> 2;
    const int g = w >> 2;
    const int cb = 32 * (w & 3);
    const bool is_logit = (g == 0);

    const float* W  = (g == 0) ? Ww  : (g == 1) ? xuw : (g == 2) ? xrw : xgw;
    const float* Bv = (g == 0) ? Wb  : (g == 1) ? xub : (g == 2) ? xrb : xgb;

    uint32_t bfr[4][8][2];
    float2 bs[4];
    #pragma unroll
    for (int ct = 0; ct < 4; ct++) {
        const int n = cb + 8 * ct + l4;
        bs[ct] = *(const float2*)&Bv[cb + 8 * ct + 2 * q];
        #pragma unroll
        for (int kt = 0; kt < 8; kt++) {
            float2 wa = *(const float2*)&W[n * 128 + kt * 16 + 2 * q];
            float2 wb = *(const float2*)&W[n * 128 + kt * 16 + 2 * q + 8];
            bfr[ct][kt][0] = f2h2(wa.x, wa.y);
            bfr[ct][kt][1] = f2h2(wb.x, wb.y);
        }
    }

    const uint32_t abase = smem_u32(is_logit ? tg16 : hs16)
                         + (lane & 15) * 272 + (lane >> 4) * 16;
    uint32_t* swbw = swb + (w - 4) * 320;
    const int gc0 = (g - 1) * 128 + cb;

    for (int tile = blockIdx.x; tile < K1_TILES; tile += 148) {
        const size_t row0 = (size_t)tile * 64;
        __syncthreads();
        #pragma unroll
        for (int j = 0; j < 8; j++) {
            int idx = t + 512 * j;
            int r = idx >> 6, c2 = idx & 63;
            float2 tv = *(const float2*)&targets[(row0 + r) * 128 + 2 * c2];
            float2 hv = *(const float2*)&hist[(row0 + r) * 128 + 2 * c2];
            *(__half2*)&tg16[r * 136 + 2 * c2] = __floats2half2_rn(tv.x, tv.y);
            *(__half2*)&hs16[r * 136 + 2 * c2] = __floats2half2_rn(hv.x, hv.y);
        }
        __syncthreads();

        #pragma unroll
        for (int mt = 0; mt < 4; mt++) {
            float acc[4][4];
            #pragma unroll
            for (int ct = 0; ct < 4; ct++) {
                if (is_logit) {
                    acc[ct][0] = acc[ct][1] = acc[ct][2] = acc[ct][3] = 0.f;
                } else {
                    acc[ct][0] = bs[ct].x; acc[ct][1] = bs[ct].y;
                    acc[ct][2] = bs[ct].x; acc[ct][3] = bs[ct].y;
                }
            }
            const uint32_t ab = abase + mt * 4352;
            #pragma unroll
            for (int kc = 0; kc < 2; kc++) {
                uint32_t af[4][4];
                #pragma unroll
                for (int k4 = 0; k4 < 4; k4++)
                    ldmatrix_x4(af[k4], ab + (4 * kc + k4) * 32);
                #pragma unroll
                for (int ct = 0; ct < 4; ct++)
                    #pragma unroll
                    for (int k4 = 0; k4 < 4; k4++)
                        mma16816(acc[ct], af[k4], bfr[ct][4 * kc + k4][0], bfr[ct][4 * kc + k4][1]);
            }
            const int r0 = mt * 16 + l4, r1 = r0 + 8;
            if (is_logit) {
                float p0 = 0.f, p1 = 0.f;
                #pragma unroll
                for (int ct = 0; ct < 4; ct++) {
                    const int col = cb + 8 * ct + 2 * q;
                    float2 h0 = __half22float2(*(const __half2*)&hs16[r0 * 136 + col]);
                    float2 h1 = __half22float2(*(const __half2*)&hs16[r1 * 136 + col]);
                    p0 += (acc[ct][0] + bs[ct].x) * h0.x + (acc[ct][1] + bs[ct].y) * h0.y;
                    p1 += (acc[ct][2] + bs[ct].x) * h1.x + (acc[ct][3] + bs[ct].y) * h1.y;
                }
                p0 += __shfl_xor_sync(~0u, p0, 1); p0 += __shfl_xor_sync(~0u, p0, 2);
                p1 += __shfl_xor_sync(~0u, p1, 1); p1 += __shfl_xor_sync(~0u, p1, 2);
                if (q == 0) {
                    lgp[w * 64 + r0] = p0;
                    lgp[w * 64 + r1] = p1;
                }
            } else {
                #pragma unroll
                for (int ct = 0; ct < 4; ct++) {
                    swbw[l4 * 20 + ct * 4 + q]       = f2h2(acc[ct][0], acc[ct][1]);
                    swbw[(l4 + 8) * 20 + ct * 4 + q] = f2h2(acc[ct][2], acc[ct][3]);
                }
                __syncwarp();
                #pragma unroll
                for (int i = lane; i < 256; i += 32) {
                    int row = i >> 4, c = i & 15;
                    uint32_t v = swbw[row * 20 + c];
                    *(uint32_t*)&g_xall16[(row0 + mt * 16 + row) * 384 + gc0 + 2 * c] = v;
                }
                __syncwarp();
            }
        }
        __syncthreads();
        if (t < 64)
            g_logits[row0 + t] = lgp[t] + lgp[64 + t] + lgp[128 + t] + lgp[192 + t];
    }
}

// ================= K2: softmax over T =================
__global__ void k2_softmax()
{
    __shared__ float red[256];
    const int b = blockIdx.x, t = threadIdx.x;
    float v = (t < 200) ? g_logits[b * 200 + t] : -1e30f;
    red[t] = v; __syncthreads();
    for (int s = 128; s; s >>= 1) { if (t < s) red[t] = fmaxf(red[t], red[t + s]); __syncthreads(); }
    float mx = red[0]; __syncthreads();
    float e = (t < 200) ? __expf(v - mx) : 0.f;
    red[t] = e; __syncthreads();
    for (int s = 128; s; s >>= 1) { if (t < s) red[t] += red[t + s]; __syncthreads(); }
    float inv = __fdividef(1.f, red[0]);
    if (t < 200) g_att[b * 200 + t] = e * inv;
}

// ================= K3: GRU scan, distance-2 x prefetch + fused final linear =================
#define K3_HBUF 4352
#define XPAD 196

__global__ __launch_bounds__(256) void k3_scan(
    const float* __restrict__ targets,
    const float* __restrict__ huw, const float* __restrict__ hub,
    const float* __restrict__ hrw, const float* __restrict__ hrb,
    const float* __restrict__ hgw, const float* __restrict__ hgb,
    const float* __restrict__ lnw, const float* __restrict__ lnb,
    float* __restrict__ out)
{
    __shared__ __align__(16) __half hsm[2 * 16 * 136];
    __shared__ __align__(16) uint32_t xbuf[2][8 * XPAD];
    __shared__ __align__(16) float attall[8][200];
    __shared__ __align__(16) float xs[8][260];
    const int t = threadIdx.x, w = t >> 5, lane = t & 31;
    const int q = lane & 3, l4 = lane >> 2;
    const size_t rowb = (size_t)blockIdx.x * 8;

    uint32_t bfr[3][2][8][2];
    float2 bias2[3][2];
    #pragma unroll
    for (int g = 0; g < 3; g++) {
        const float* W  = (g == 0) ? huw : (g == 1) ? hrw : hgw;
        const float* Bv = (g == 0) ? hub : (g == 1) ? hrb : hgb;
        #pragma unroll
        for (int j = 0; j < 2; j++) {
            const int n = 16 * w + 8 * j + l4;
            bias2[g][j] = *(const float2*)&Bv[16 * w + 8 * j + 2 * q];
            #pragma unroll
            for (int kt = 0; kt < 8; kt++) {
                float2 wa = *(const float2*)&W[n * 128 + kt * 16 + 2 * q];
                float2 wb = *(const float2*)&W[n * 128 + kt * 16 + 2 * q + 8];
                bfr[g][j][kt][0] = f2h2(wa.x, wa.y);
                bfr[g][j][kt][1] = f2h2(wb.x, wb.y);
            }
        }
    }
    for (int i = t; i < 2 * 16 * 136; i += 256) hsm[i] = __float2half(0.f);

    // preload ALL att for this CTA's 8 rows (removes att LDG from the loop)
    for (int i = t; i < 1600; i += 256) {
        int row = i / 200, s = i % 200;
        attall[row][s] = g_att[(rowb + row) * 200 + s];
    }
    // step-0 x directly into xbuf[0]; step-1 x into registers (STS'd at step 0)
    for (int i = t; i < 1536; i += 256) {
        int row = i / 192, col = i % 192;
        xbuf[0][row * XPAD + col] =
            *(const uint32_t*)&g_xall16[((rowb + row) * 200) * 384 + col * 2];
    }
    uint32_t xr6[6];
    #pragma unroll
    for (int j = 0; j < 6; j++) {
        int idx = t + j * 256;
        int row = idx / 192, col = idx % 192;
        xr6[j] = *(const uint32_t*)&g_xall16[((rowb + row) * 200 + 1) * 384 + col * 2];
    }
    __syncthreads();

    float hm[2][2] = {{0.f, 0.f}, {0.f, 0.f}};
    const uint32_t hb0 = smem_u32(hsm) + (lane & 15) * 272 + (lane >> 4) * 16;

    for (int step = 0; step < 200; step++) {
        const int rb = step & 1, wbuf = 1 - rb;

        // 1) publish step+1's x (held in regs since step-1) — buffer free since end of step-1
        if (step < 199) {
            #pragma unroll
            for (int j = 0; j < 6; j++) {
                int idx = t + j * 256;
                int row = idx / 192, col = idx % 192;
                xbuf[wbuf][row * XPAD + col] = xr6[j];
            }
        }
        // 2) issue LDG for step+2 (lands over a full step body -> DRAM latency hidden)
        if (step < 198) {
            #pragma unroll
            for (int j = 0; j < 6; j++) {
                int idx = t + j * 256;
                int row = idx / 192, col = idx % 192;
                xr6[j] = *(const uint32_t*)&g_xall16[((rowb + row) * 200 + step + 2) * 384 + col * 2];
            }
        }

        // 3) gather this step's x from smem (conflict-free)
        float acc[3][2][4];
        float xg2[2][2];
        #pragma unroll
        for (int j = 0; j < 2; j++) {
            const int ci = 8 * w + 4 * j + q;
            float2 vu = __half22float2(*(__half2*)&xbuf[rb][l4 * XPAD + ci]);
            float2 vr = __half22float2(*(__half2*)&xbuf[rb][l4 * XPAD + 64 + ci]);
            float2 vg = __half22float2(*(__half2*)&xbuf[rb][l4 * XPAD + 128 + ci]);
            acc[0][j][0] = vu.x; acc[0][j][1] = vu.y; acc[0][j][2] = 0.f; acc[0][j][3] = 0.f;
            acc[1][j][0] = vr.x; acc[1][j][1] = vr.y; acc[1][j][2] = 0.f; acc[1][j][3] = 0.f;
            xg2[j][0] = vg.x; xg2[j][1] = vg.y;
            acc[2][j][0] = acc[2][j][1] = acc[2][j][2] = acc[2][j][3] = 0.f;
        }
        const float a0 = attall[l4][step];

        #pragma unroll
        for (int kt = 0; kt < 8; kt++) {
            uint32_t afr[4];
            ldmatrix_x4(afr, hb0 + rb * K3_HBUF + kt * 32);
            #pragma unroll
            for (int g = 0; g < 3; g++) {
                mma16816(acc[g][0], afr, bfr[g][0][kt][0], bfr[g][0][kt][1]);
                mma16816(acc[g][1], afr, bfr[g][1][kt][0], bfr[g][1][kt][1]);
            }
        }

        float hn[2][2];
        #pragma unroll
        for (int j = 0; j < 2; j++) {
            #pragma unroll
            for (int e = 0; e < 2; e++) {
                const float bU = e ? bias2[0][j].y : bias2[0][j].x;
                const float bR = e ? bias2[1][j].y : bias2[1][j].x;
                const float bG = e ? bias2[2][j].y : bias2[2][j].x;
                float u = fmaf(tanhapx(0.5f * (acc[0][j][e] + bU)), 0.5f, 0.5f) * a0;
                float r = fmaf(tanhapx(0.5f * (acc[1][j][e] + bR)), 0.5f, 0.5f);
                float pre = xg2[j][e] + r * (acc[2][j][e] + bG);
                float gg = tanhapx(pre);
                hn[j][e] = fmaf(u, gg - hm[j][e], hm[j][e]);
            }
        }
        char* hw = (char*)hsm + wbuf * K3_HBUF;
        #pragma unroll
        for (int j = 0; j < 2; j++) {
            *(uint32_t*)(hw + l4 * 272 + (16 * w + 8 * j + 2 * q) * 2) = f2h2(hn[j][0], hn[j][1]);
            hm[j][0] = hn[j][0]; hm[j][1] = hn[j][1];
        }
        __syncthreads();
    }

    // ---- fused final linear: out = [h, targets[:,0]] @ ln2_w^T + b ----
    #pragma unroll
    for (int j = 0; j < 2; j++) {
        xs[l4][16 * w + 8 * j + 2 * q]     = hm[j][0];
        xs[l4][16 * w + 8 * j + 2 * q + 1] = hm[j][1];
    }
    for (int i = t; i < 1024; i += 256) {
        int bb = i >> 7, c = i & 127;
        xs[bb][128 + c] = targets[(size_t)(rowb + bb) * 200 * 128 + c];
    }
    __syncthreads();
    const int col = t & 127, grp = t >> 7;
    float acc4[4];
    const float bv = lnb[col];
    #pragma unroll
    for (int i = 0; i < 4; i++) acc4[i] = bv;
    const float4* wr = (const float4*)(lnw + (size_t)col * 256);
    #pragma unroll 4
    for (int k = 0; k < 64; k++) {
        float4 wv = wr[k];
        #pragma unroll
        for (int i = 0; i < 4; i++) {
            float4 xv = *(const float4*)&xs[grp * 4 + i][k * 4];
            acc4[i] += wv.x * xv.x + wv.y * xv.y + wv.z * xv.z + wv.w * xv.w;
        }
    }
    #pragma unroll
    for (int i = 0; i < 4; i++)
        out[(rowb + grp * 4 + i) * 128 + col] = acc4[i];
}

extern "C" void kernel_launch(void* const* d_in, const int* in_sizes, int n_in,
                              void* d_out, int out_size)
{
    const float* targets = (const float*)d_in[0];
    const float* hist    = (const float*)d_in[1];
    const float* Ww  = (const float*)d_in[2];  const float* Wb  = (const float*)d_in[3];
    const float* xuw = (const float*)d_in[4];  const float* xub = (const float*)d_in[5];
    const float* huw = (const float*)d_in[6];  const float* hub = (const float*)d_in[7];
    const float* xrw = (const float*)d_in[8];  const float* xrb = (const float*)d_in[9];
    const float* hrw = (const float*)d_in[10]; const float* hrb = (const float*)d_in[11];
    const float* xgw = (const float*)d_in[12]; const float* xgb = (const float*)d_in[13];
    const float* hgw = (const float*)d_in[14]; const float* hgb = (const float*)d_in[15];
    const float* lnw = (const float*)d_in[16]; const float* lnb = (const float*)d_in[17];
    float* out = (float*)d_out;

    cudaFuncSetAttribute(k1_ff, cudaFuncAttributeMaxDynamicSharedMemorySize, K1_SMEM);

    k1_ff<<<148, 512, K1_SMEM>>>(targets, hist, Ww, Wb, xuw, xub, xrw, xrb, xgw, xgb);
    k2_softmax<<<1024, 256>>>();
    k3_scan<<<128, 256>>>(targets, huw, hub, hrw, hrb, hgw, hgb, lnw, lnb, out);
}

// round 12
// speedup vs baseline: 1.0627x; 1.0627x over previous
#include <cuda_runtime.h>
#include <cuda_fp16.h>
#include <cstdint>

// B=1024, T=200, IN=H=128. rows = 204800.
__device__ __half g_xall16[(size_t)204800 * 384];   // [flat row][xu|xr|xg] fp16, biases folded
__device__ float g_logits[204800];
__device__ float g_att[204800];

__device__ __forceinline__ uint32_t smem_u32(const void* p) {
    return (uint32_t)__cvta_generic_to_shared(p);
}
__device__ __forceinline__ void ldmatrix_x4(uint32_t a[4], uint32_t addr) {
    asm volatile("ldmatrix.sync.aligned.m8n8.x4.shared.b16 {%0,%1,%2,%3}, [%4];"
                 : "=r"(a[0]), "=r"(a[1]), "=r"(a[2]), "=r"(a[3]) : "r"(addr));
}
__device__ __forceinline__ void ldmatrix_x4_trans(uint32_t a[4], uint32_t addr) {
    asm volatile("ldmatrix.sync.aligned.m8n8.x4.trans.shared.b16 {%0,%1,%2,%3}, [%4];"
                 : "=r"(a[0]), "=r"(a[1]), "=r"(a[2]), "=r"(a[3]) : "r"(addr));
}
__device__ __forceinline__ void mma16816(float c[4], const uint32_t a[4], uint32_t b0, uint32_t b1) {
    asm volatile("mma.sync.aligned.m16n8k16.row.col.f32.f16.f16.f32 "
                 "{%0,%1,%2,%3},{%4,%5,%6,%7},{%8,%9},{%0,%1,%2,%3};"
                 : "+f"(c[0]), "+f"(c[1]), "+f"(c[2]), "+f"(c[3])
                 : "r"(a[0]), "r"(a[1]), "r"(a[2]), "r"(a[3]), "r"(b0), "r"(b1));
}
__device__ __forceinline__ uint32_t f2h2(float x, float y) {
    __half2 h = __floats2half2_rn(x, y);
    return *reinterpret_cast<uint32_t*>(&h);
}
__device__ __forceinline__ float tanhapx(float x) {
    float y; asm("tanh.approx.f32 %0, %1;" : "=f"(y) : "f"(x)); return y;
}

// ================= K1: logits + x projections, register-resident weights =================
#define K1_HS_OFF  17408
#define K1_SWB_OFF 34816
#define K1_LGP_OFF 50176
#define K1_SMEM    51200
#define K1_TILES   3200

__global__ __launch_bounds__(512) void k1_ff(
    const float* __restrict__ targets, const float* __restrict__ hist,
    const float* __restrict__ Ww,  const float* __restrict__ Wb,
    const float* __restrict__ xuw, const float* __restrict__ xub,
    const float* __restrict__ xrw, const float* __restrict__ xrb,
    const float* __restrict__ xgw, const float* __restrict__ xgb)
{
    extern __shared__ char sm[];
    __half* tg16 = (__half*)sm;
    __half* hs16 = (__half*)(sm + K1_HS_OFF);
    uint32_t* swb = (uint32_t*)(sm + K1_SWB_OFF);
    float* lgp = (float*)(sm + K1_LGP_OFF);

    const int t = threadIdx.x, w = t >> 5, lane = t & 31;
    const int q = lane & 3, l4 = lane >> 2;
    const int g = w >> 2;
    const int cb = 32 * (w & 3);
    const bool is_logit = (g == 0);

    const float* W  = (g == 0) ? Ww  : (g == 1) ? xuw : (g == 2) ? xrw : xgw;
    const float* Bv = (g == 0) ? Wb  : (g == 1) ? xub : (g == 2) ? xrb : xgb;

    uint32_t bfr[4][8][2];
    float2 bs[4];
    #pragma unroll
    for (int ct = 0; ct < 4; ct++) {
        const int n = cb + 8 * ct + l4;
        bs[ct] = *(const float2*)&Bv[cb + 8 * ct + 2 * q];
        #pragma unroll
        for (int kt = 0; kt < 8; kt++) {
            float2 wa = *(const float2*)&W[n * 128 + kt * 16 + 2 * q];
            float2 wb = *(const float2*)&W[n * 128 + kt * 16 + 2 * q + 8];
            bfr[ct][kt][0] = f2h2(wa.x, wa.y);
            bfr[ct][kt][1] = f2h2(wb.x, wb.y);
        }
    }

    const uint32_t abase = smem_u32(is_logit ? tg16 : hs16)
                         + (lane & 15) * 272 + (lane >> 4) * 16;
    uint32_t* swbw = swb + (w - 4) * 320;
    const int gc0 = (g - 1) * 128 + cb;

    for (int tile = blockIdx.x; tile < K1_TILES; tile += 148) {
        const size_t row0 = (size_t)tile * 64;
        __syncthreads();
        #pragma unroll
        for (int j = 0; j < 8; j++) {
            int idx = t + 512 * j;
            int r = idx >> 6, c2 = idx & 63;
            float2 tv = *(const float2*)&targets[(row0 + r) * 128 + 2 * c2];
            float2 hv = *(const float2*)&hist[(row0 + r) * 128 + 2 * c2];
            *(__half2*)&tg16[r * 136 + 2 * c2] = __floats2half2_rn(tv.x, tv.y);
            *(__half2*)&hs16[r * 136 + 2 * c2] = __floats2half2_rn(hv.x, hv.y);
        }
        __syncthreads();

        #pragma unroll
        for (int mt = 0; mt < 4; mt++) {
            float acc[4][4];
            #pragma unroll
            for (int ct = 0; ct < 4; ct++) {
                if (is_logit) {
                    acc[ct][0] = acc[ct][1] = acc[ct][2] = acc[ct][3] = 0.f;
                } else {
                    acc[ct][0] = bs[ct].x; acc[ct][1] = bs[ct].y;
                    acc[ct][2] = bs[ct].x; acc[ct][3] = bs[ct].y;
                }
            }
            const uint32_t ab = abase + mt * 4352;
            #pragma unroll
            for (int kc = 0; kc < 2; kc++) {
                uint32_t af[4][4];
                #pragma unroll
                for (int k4 = 0; k4 < 4; k4++)
                    ldmatrix_x4(af[k4], ab + (4 * kc + k4) * 32);
                #pragma unroll
                for (int ct = 0; ct < 4; ct++)
                    #pragma unroll
                    for (int k4 = 0; k4 < 4; k4++)
                        mma16816(acc[ct], af[k4], bfr[ct][4 * kc + k4][0], bfr[ct][4 * kc + k4][1]);
            }
            const int r0 = mt * 16 + l4, r1 = r0 + 8;
            if (is_logit) {
                float p0 = 0.f, p1 = 0.f;
                #pragma unroll
                for (int ct = 0; ct < 4; ct++) {
                    const int col = cb + 8 * ct + 2 * q;
                    float2 h0 = __half22float2(*(const __half2*)&hs16[r0 * 136 + col]);
                    float2 h1 = __half22float2(*(const __half2*)&hs16[r1 * 136 + col]);
                    p0 += (acc[ct][0] + bs[ct].x) * h0.x + (acc[ct][1] + bs[ct].y) * h0.y;
                    p1 += (acc[ct][2] + bs[ct].x) * h1.x + (acc[ct][3] + bs[ct].y) * h1.y;
                }
                p0 += __shfl_xor_sync(~0u, p0, 1); p0 += __shfl_xor_sync(~0u, p0, 2);
                p1 += __shfl_xor_sync(~0u, p1, 1); p1 += __shfl_xor_sync(~0u, p1, 2);
                if (q == 0) {
                    lgp[w * 64 + r0] = p0;
                    lgp[w * 64 + r1] = p1;
                }
            } else {
                #pragma unroll
                for (int ct = 0; ct < 4; ct++) {
                    swbw[l4 * 20 + ct * 4 + q]       = f2h2(acc[ct][0], acc[ct][1]);
                    swbw[(l4 + 8) * 20 + ct * 4 + q] = f2h2(acc[ct][2], acc[ct][3]);
                }
                __syncwarp();
                #pragma unroll
                for (int i = lane; i < 256; i += 32) {
                    int row = i >> 4, c = i & 15;
                    uint32_t v = swbw[row * 20 + c];
                    *(uint32_t*)&g_xall16[(row0 + mt * 16 + row) * 384 + gc0 + 2 * c] = v;
                }
                __syncwarp();
            }
        }
        __syncthreads();
        if (t < 64)
            g_logits[row0 + t] = lgp[t] + lgp[64 + t] + lgp[128 + t] + lgp[192 + t];
    }
}

// ================= K2: softmax over T =================
__global__ void k2_softmax()
{
    __shared__ float red[256];
    const int b = blockIdx.x, t = threadIdx.x;
    float v = (t < 200) ? g_logits[b * 200 + t] : -1e30f;
    red[t] = v; __syncthreads();
    for (int s = 128; s; s >>= 1) { if (t < s) red[t] = fmaxf(red[t], red[t + s]); __syncthreads(); }
    float mx = red[0]; __syncthreads();
    float e = (t < 200) ? __expf(v - mx) : 0.f;
    red[t] = e; __syncthreads();
    for (int s = 128; s; s >>= 1) { if (t < s) red[t] += red[t + s]; __syncthreads(); }
    float inv = __fdividef(1.f, red[0]);
    if (t < 200) g_att[b * 200 + t] = e * inv;
}

// ================= K3: transposed GRU scan (W·h^T, batch in n=8) + fused final linear =================
// 128 CTAs x 256 thr (8 warps); warp w owns output cols [16w,16w+16) of all 3 gates.
// Weights = register A-fragments. h stored transposed hT[128 cols][8 batch] fp16 (16B rows):
// ldmatrix.x4.trans B-frags, linear conflict-free addresses. 1 barrier/step.
#define XPAD 196

__global__ __launch_bounds__(256) void k3_scan(
    const float* __restrict__ targets,
    const float* __restrict__ huw, const float* __restrict__ hub,
    const float* __restrict__ hrw, const float* __restrict__ hrb,
    const float* __restrict__ hgw, const float* __restrict__ hgb,
    const float* __restrict__ lnw, const float* __restrict__ lnb,
    float* __restrict__ out)
{
    __shared__ __align__(16) __half hT[2][128 * 8];     // 2 x 2048 B
    __shared__ __align__(16) uint32_t xbuf[2][8 * XPAD];
    __shared__ float attbuf[2][8];
    __shared__ __align__(16) float xs[8][260];
    const int t = threadIdx.x, w = t >> 5, lane = t & 31;
    const int q = lane & 3, l4 = lane >> 2;
    const size_t rowb = (size_t)blockIdx.x * 8;

    // ---- weight A-fragments (registers, loaded once): [gate][kt][4] ----
    // a0=(m=l4, k=2q..2q+1) a1=(l4+8, 2q..) a2=(l4, 2q+8..) a3=(l4+8, 2q+8..)
    uint32_t afr[3][8][4];
    float bias_[3][2];
    #pragma unroll
    for (int g = 0; g < 3; g++) {
        const float* W  = (g == 0) ? huw : (g == 1) ? hrw : hgw;
        const float* Bv = (g == 0) ? hub : (g == 1) ? hrb : hgb;
        bias_[g][0] = Bv[16 * w + l4];
        bias_[g][1] = Bv[16 * w + l4 + 8];
        #pragma unroll
        for (int kt = 0; kt < 8; kt++) {
            const float* bp = W + (16 * w + l4) * 128 + kt * 16 + 2 * q;
            float2 v0 = *(const float2*)(bp);
            float2 v2 = *(const float2*)(bp + 8);
            float2 v1 = *(const float2*)(bp + 8 * 128);
            float2 v3 = *(const float2*)(bp + 8 * 128 + 8);
            afr[g][kt][0] = f2h2(v0.x, v0.y);
            afr[g][kt][1] = f2h2(v1.x, v1.y);
            afr[g][kt][2] = f2h2(v2.x, v2.y);
            afr[g][kt][3] = f2h2(v3.x, v3.y);
        }
    }
    // zero both hT buffers
    for (int i = t; i < 2048; i += 256) ((__half*)hT)[i] = __float2half(0.f);

    // step-0 x/att into buffer 0 (coalesced)
    for (int i = t; i < 1536; i += 256) {
        int row = i / 192, col = i % 192;
        xbuf[0][row * XPAD + col] =
            *(const uint32_t*)&g_xall16[((rowb + row) * 200) * 384 + col * 2];
    }
    if (t < 8) attbuf[0][t] = g_att[(rowb + t) * 200];
    __syncthreads();

    float hm[4] = {0.f, 0.f, 0.f, 0.f};   // (col l4,b 2q),(l4,2q+1),(l4+8,2q),(l4+8,2q+1)
    const uint32_t hTb = smem_u32(hT) + lane * 16;
    const int colA = 16 * w + l4, colB = colA + 8;

    for (int step = 0; step < 200; step++) {
        const int rb = step & 1, wb = 1 - rb;

        // prefetch next step's x/att (distance 1, proven in R9)
        uint32_t xr6[6]; float attr = 0.f;
        if (step < 199) {
            #pragma unroll
            for (int j = 0; j < 6; j++) {
                int idx = t + j * 256;
                int row = idx / 192, col = idx % 192;
                xr6[j] = *(const uint32_t*)&g_xall16[((rowb + row) * 200 + step + 1) * 384 + col * 2];
            }
            if (t < 8) attr = g_att[(rowb + t) * 200 + step + 1];
        }

        // acc init from x (scalar LDS; layout [batch row][gate*128 + col] halves)
        const char* xb = (const char*)xbuf[rb];
        float acc[3][4], xg4[4];
        #pragma unroll
        for (int c = 0; c < 4; c++) {
            const int bofs = (2 * q + (c & 1)) * (XPAD * 4) + ((c >> 1) ? colB : colA) * 2;
            acc[0][c] = __half2float(*(const __half*)(xb + bofs));
            acc[1][c] = __half2float(*(const __half*)(xb + bofs + 256));
            xg4[c]    = __half2float(*(const __half*)(xb + bofs + 512));
            acc[2][c] = 0.f;
        }
        const float attv0 = attbuf[rb][2 * q], attv1 = attbuf[rb][2 * q + 1];

        // B-frags from hT (x4 trans, linear addresses)
        uint32_t bf[8][2];
        #pragma unroll
        for (int j = 0; j < 4; j++) {
            uint32_t r4[4];
            ldmatrix_x4_trans(r4, hTb + rb * 2048 + j * 512);
            bf[2 * j][0] = r4[0]; bf[2 * j][1] = r4[1];
            bf[2 * j + 1][0] = r4[2]; bf[2 * j + 1][1] = r4[3];
        }
        #pragma unroll
        for (int kt = 0; kt < 8; kt++) {
            mma16816(acc[0], afr[0][kt], bf[kt][0], bf[kt][1]);
            mma16816(acc[1], afr[1][kt], bf[kt][0], bf[kt][1]);
            mma16816(acc[2], afr[2][kt], bf[kt][0], bf[kt][1]);
        }

        float hn[4];
        #pragma unroll
        for (int c = 0; c < 4; c++) {
            const int hi = c >> 1;
            const float ae = (c & 1) ? attv1 : attv0;
            float u = fmaf(tanhapx(0.5f * (acc[0][c] + bias_[0][hi])), 0.5f, 0.5f) * ae;
            float r = fmaf(tanhapx(0.5f * (acc[1][c] + bias_[1][hi])), 0.5f, 0.5f);
            float pre = xg4[c] + r * (acc[2][c] + bias_[2][hi]);
            float gg = tanhapx(pre);
            hn[c] = fmaf(u, gg - hm[c], hm[c]);
        }
        // publish hT[wb]: row = col (16B), half2 at batch 2q — banks 4*l4+q distinct
        *(uint32_t*)((char*)hT[wb] + colA * 16 + 4 * q) = f2h2(hn[0], hn[1]);
        *(uint32_t*)((char*)hT[wb] + colB * 16 + 4 * q) = f2h2(hn[2], hn[3]);
        hm[0] = hn[0]; hm[1] = hn[1]; hm[2] = hn[2]; hm[3] = hn[3];

        if (step < 199) {
            #pragma unroll
            for (int j = 0; j < 6; j++) {
                int idx = t + j * 256;
                int row = idx / 192, col = idx % 192;
                xbuf[wb][row * XPAD + col] = xr6[j];
            }
            if (t < 8) attbuf[wb][t] = attr;
        }
        __syncthreads();
    }

    // ---- fused final linear: out = [h, targets[:,0]] @ ln2_w^T + b ----
    xs[2 * q][colA]     = hm[0];
    xs[2 * q + 1][colA] = hm[1];
    xs[2 * q][colB]     = hm[2];
    xs[2 * q + 1][colB] = hm[3];
    for (int i = t; i < 1024; i += 256) {
        int bb = i >> 7, c = i & 127;
        xs[bb][128 + c] = targets[(size_t)(rowb + bb) * 200 * 128 + c];
    }
    __syncthreads();
    const int col = t & 127, grp = t >> 7;
    float acc4[4];
    const float bv = lnb[col];
    #pragma unroll
    for (int i = 0; i < 4; i++) acc4[i] = bv;
    const float4* wr = (const float4*)(lnw + (size_t)col * 256);
    #pragma unroll 4
    for (int k = 0; k < 64; k++) {
        float4 wv = wr[k];
        #pragma unroll
        for (int i = 0; i < 4; i++) {
            float4 xv = *(const float4*)&xs[grp * 4 + i][k * 4];
            acc4[i] += wv.x * xv.x + wv.y * xv.y + wv.z * xv.z + wv.w * xv.w;
        }
    }
    #pragma unroll
    for (int i = 0; i < 4; i++)
        out[(rowb + grp * 4 + i) * 128 + col] = acc4[i];
}

extern "C" void kernel_launch(void* const* d_in, const int* in_sizes, int n_in,
                              void* d_out, int out_size)
{
    const float* targets = (const float*)d_in[0];
    const float* hist    = (const float*)d_in[1];
    const float* Ww  = (const float*)d_in[2];  const float* Wb  = (const float*)d_in[3];
    const float* xuw = (const float*)d_in[4];  const float* xub = (const float*)d_in[5];
    const float* huw = (const float*)d_in[6];  const float* hub = (const float*)d_in[7];
    const float* xrw = (const float*)d_in[8];  const float* xrb = (const float*)d_in[9];
    const float* hrw = (const float*)d_in[10]; const float* hrb = (const float*)d_in[11];
    const float* xgw = (const float*)d_in[12]; const float* xgb = (const float*)d_in[13];
    const float* hgw = (const float*)d_in[14]; const float* hgb = (const float*)d_in[15];
    const float* lnw = (const float*)d_in[16]; const float* lnb = (const float*)d_in[17];
    float* out = (float*)d_out;

    cudaFuncSetAttribute(k1_ff, cudaFuncAttributeMaxDynamicSharedMemorySize, K1_SMEM);

    k1_ff<<<148, 512, K1_SMEM>>>(targets, hist, Ww, Wb, xuw, xub, xrw, xrb, xgw, xgb);
    k2_softmax<<<1024, 256>>>();
    k3_scan<<<128, 256>>>(targets, huw, hub, hrw, hrb, hgw, hgb, lnw, lnb, out);
}